// round 16
// baseline (speedup 1.0000x reference)
#include <cuda_runtime.h>
#include <cuda_bf16.h>
#include <cuda_fp16.h>
#include <math.h>
#include <stdint.h>

#define SEQ 4096
#define NB 4
#define HID 1024
#define HD 256
#define MTOT (NB*SEQ)
#define DW 256            // gamma^256: measured truncation cost ~1e-4 in quadrature

typedef unsigned long long u64;

// ---------------- static device scratch (no cudaMalloc allowed) ----------------
__device__ __half g_Qh[(size_t)MTOT*HD];    // recentered xpos scale, fp16
__device__ __half g_Kh[(size_t)MTOT*HD];
__device__ __half g_Vf[(size_t)MTOT*HD];
__device__ __half g_Xh[(size_t)MTOT*HID];
__device__ __half g_Wh[3*HID*HD];           // [z][k][n], W*1024 fp16
__device__ float g_cosQ[SEQ*128];
__device__ float g_sinQ[SEQ*128];
__device__ float g_cosK[SEQ*128];
__device__ float g_sinK[SEQ*128];
__device__ float g_gamma[SEQ];

// ---------------- mma / async helpers (baseline PTX, sm_80+ ISA only) ----------------
__device__ __forceinline__ uint32_t smem_u32(const void* p) {
    uint32_t a;
    asm("{ .reg .u64 t; cvta.to.shared.u64 t, %1; cvt.u32.u64 %0, t; }" : "=r"(a) : "l"(p));
    return a;
}
__device__ __forceinline__ void cp16(uint32_t dst, const void* src) {
    asm volatile("cp.async.cg.shared.global [%0], [%1], 16;" :: "r"(dst), "l"(src));
}
#define CP_COMMIT()  asm volatile("cp.async.commit_group;" ::: "memory")
#define CP_WAIT(n)   asm volatile("cp.async.wait_group %0;" :: "n"(n) : "memory")

__device__ __forceinline__ void ldsm4(uint32_t (&r)[4], uint32_t a) {
    asm volatile("ldmatrix.sync.aligned.m8n8.x4.shared.b16 {%0,%1,%2,%3}, [%4];"
                 : "=r"(r[0]), "=r"(r[1]), "=r"(r[2]), "=r"(r[3]) : "r"(a));
}
__device__ __forceinline__ void ldsm4t(uint32_t (&r)[4], uint32_t a) {
    asm volatile("ldmatrix.sync.aligned.m8n8.x4.trans.shared.b16 {%0,%1,%2,%3}, [%4];"
                 : "=r"(r[0]), "=r"(r[1]), "=r"(r[2]), "=r"(r[3]) : "r"(a));
}
__device__ __forceinline__ void mma16816h(float* d, const uint32_t* a, uint32_t b0, uint32_t b1) {
    asm volatile(
        "mma.sync.aligned.m16n8k16.row.col.f32.f16.f16.f32 "
        "{%0,%1,%2,%3}, {%4,%5,%6,%7}, {%8,%9}, {%0,%1,%2,%3};"
        : "+f"(d[0]), "+f"(d[1]), "+f"(d[2]), "+f"(d[3])
        : "r"(a[0]), "r"(a[1]), "r"(a[2]), "r"(a[3]), "r"(b0), "r"(b1));
}
__device__ __forceinline__ uint32_t fp16pair(float a, float b) {
    __half2 t; t.x = __float2half(a); t.y = __float2half(b);
    uint32_t r; asm("mov.b32 %0, %1;" : "=r"(r) : "r"(*(uint32_t*)&t)); return r;
}

// ---------------- fused prep: splitx | splitw+gamma | xpos tables ----------------
// One launch, partitioned by blockIdx. No cross-block reads of written data:
// tables blocks compute invf/l2sb inline with the SAME fp64 math (bit-identical).
#define PREP_BX 8192               // splitx: X -> fp16, 8 floats/thread
#define PREP_BW 3072               // W*1024 -> fp16 (+ gamma table)
#define PREP_BT 2048               // xpos tables, 2 pos per block

__global__ void prep_kernel(const float* __restrict__ X,
                            const float* __restrict__ WQ,
                            const float* __restrict__ WK,
                            const float* __restrict__ WV) {
    int bid = blockIdx.x, tid = threadIdx.x;
    if (bid < PREP_BX) {
        // ---- splitx ----
        size_t i = (size_t)bid * 256 + tid;
        float4 a = ((const float4*)X)[2 * i];
        float4 b = ((const float4*)X)[2 * i + 1];
        uint4 o;
        o.x = fp16pair(a.x, a.y); o.y = fp16pair(a.z, a.w);
        o.z = fp16pair(b.x, b.y); o.w = fp16pair(b.z, b.w);
        ((uint4*)g_Xh)[i] = o;
    } else if (bid < PREP_BX + PREP_BW) {
        // ---- splitw + gamma ----
        int idx = (bid - PREP_BX) * 256 + tid;     // [z][k][n], 3*1024*256
        if (idx < SEQ) g_gamma[idx] = (float)pow(0.96875, (double)idx);
        int z = idx >> 18;
        int kn = idx & 0x3FFFF;
        const float* W = (z == 0) ? WQ : (z == 1 ? WK : WV);
        g_Wh[idx] = __float2half(W[kn] * 1024.0f);
    } else {
        // ---- xpos tables, RECENTERED scale ----
        int b2 = bid - PREP_BX - PREP_BW;
        int pos = b2 * 2 + (tid >> 7);
        int j = tid & 127;
        float invf = (float)pow(10000.0, -(double)j / 128.0);   // fp64-exact, as before
        float arg = (float)pos * invf;
        double ad = (double)arg;
        double qd = rint(ad * 0.63661977236758134308);
        double rd = fma(qd, -1.5707963267948966, ad);
        rd = fma(qd, -6.123233995736766e-17, rd);
        int qi = ((long long)qd) & 3;
        float rf = (float)rd;
        float sr = sinf(rf), cr = cosf(rf);
        float s, c;
        if      (qi == 0) { s =  sr; c =  cr; }
        else if (qi == 1) { s =  cr; c = -sr; }
        else if (qi == 2) { s = -sr; c = -cr; }
        else              { s = -cr; c =  sr; }
        float p  = ((float)pos - 2048.0f) * (1.0f / 512.0f);    // recentered
        double sb = ((double)(2 * j) + 0.4 * 256.0) / (1.4 * 256.0);
        float l2 = (float)log2(sb);                              // fp64-exact, as before
        float sc  = exp2f(p * l2);
        float isc = exp2f(-p * l2);
        int idx = pos * 128 + j;
        g_cosQ[idx] = c * sc;   g_sinQ[idx] = s * sc;
        g_cosK[idx] = c * isc;  g_sinK[idx] = s * isc;
    }
}

// ---------------- projection GEMM (R14 config: KC=64, 3-stage, 2 CTAs/SM) ----------------
// CTA = 128M x 128N, warp tile 32x64, K=1024 in 16 stages of KC=64, 3-stage ring.
#define PKC 64
#define PNSTG 16
#define PSTG_A 18432          // 128 rows x 144B (128B payload + 16B pad)
#define PSTG_B 16384          // 64 k-rows x 256B, swizzled
#define PSTG_BYTES (PSTG_A + PSTG_B)
#define PROJ_SMEM (3 * PSTG_BYTES)

__global__ void __launch_bounds__(256, 2) proj_mma_kernel()
{
    extern __shared__ __align__(1024) char sm[];
    uint32_t smb = smem_u32(sm);
    int tid = threadIdx.x;
    int z  = blockIdx.x >> 1;
    int n0 = (blockIdx.x & 1) * 128;
    int m0 = blockIdx.y * 128;

    const __half* Wh = g_Wh + (size_t)z * HID * HD + n0;

    // A copy: 4 chunks/thread (128 rows x 128B payload, 144B stride)
    const __half* srcA[4]; uint32_t dstA[4];
    #pragma unroll
    for (int i = 0; i < 4; i++) {
        int id = tid + i * 256;
        int m = id >> 3, c = id & 7;
        srcA[i] = g_Xh + (size_t)(m0 + m) * HID + c * 8;
        dstA[i] = (uint32_t)(m * 144 + c * 16);
    }
    // B copy: 4 chunks/thread (64 k-rows x 256B, XOR swizzle)
    const __half* srcB[4]; uint32_t dstB[4];
    #pragma unroll
    for (int i = 0; i < 4; i++) {
        int id = tid + i * 256;
        int k = id >> 4, cc = id & 15;
        srcB[i] = Wh + (size_t)k * HD + cc * 8;
        dstB[i] = (uint32_t)(PSTG_A + k * 256 +
                             ((uint32_t)((cc & 8) | ((cc ^ (k & 7)) & 7)) << 4));
    }

    int w = tid >> 5, l = tid & 31;
    int wm = w >> 1, wn = w & 1;
    int la = l & 15, hsel = l >> 4;
    uint32_t lam = (uint32_t)(la & 7);
    uint32_t brow = (uint32_t)(la * 256);
    uint32_t bnc0 = (uint32_t)(wn * 8);

    float d[2][8][4];
    #pragma unroll
    for (int mt = 0; mt < 2; mt++)
        #pragma unroll
        for (int nt = 0; nt < 8; nt++)
            #pragma unroll
            for (int r = 0; r < 4; r++) d[mt][nt][r] = 0.0f;

    // prologue: stages 0, 1
    #pragma unroll
    for (int p = 0; p < 2; p++) {
        uint32_t bb = smb + (uint32_t)p * PSTG_BYTES;
        int kt = p * PKC;
        #pragma unroll
        for (int i = 0; i < 4; i++) cp16(bb + dstA[i], srcA[i] + kt);
        #pragma unroll
        for (int i = 0; i < 4; i++) cp16(bb + dstB[i], srcB[i] + (size_t)kt * HD);
        CP_COMMIT();
    }

    int buf = 0, nbuf = 2;    // compute buffer; copy-target buffer
    for (int s = 0; s < PNSTG; s++) {
        if (s + 2 < PNSTG) {
            uint32_t bb = smb + (uint32_t)nbuf * PSTG_BYTES;
            int kt = (s + 2) * PKC;
            #pragma unroll
            for (int i = 0; i < 4; i++) cp16(bb + dstA[i], srcA[i] + kt);
            #pragma unroll
            for (int i = 0; i < 4; i++) cp16(bb + dstB[i], srcB[i] + (size_t)kt * HD);
            CP_COMMIT();
            CP_WAIT(2);
        } else if (s + 1 < PNSTG) {
            CP_WAIT(1);
        } else {
            CP_WAIT(0);
        }
        __syncthreads();

        uint32_t AS = smb + (uint32_t)buf * PSTG_BYTES;
        uint32_t BS = AS + PSTG_A;
        buf = (buf + 1 == 3) ? 0 : buf + 1;
        nbuf = (nbuf + 1 == 3) ? 0 : nbuf + 1;

        #pragma unroll
        for (int slab = 0; slab < 4; slab++) {          // four k16 slabs
            uint32_t ah[2][4];
            #pragma unroll
            for (int mt = 0; mt < 2; mt++) {
                uint32_t row = (uint32_t)(wm * 32 + mt * 16 + la);
                ldsm4(ah[mt], AS + row * 144 + (uint32_t)((slab * 2 + hsel) * 16));
            }
            uint32_t krow = BS + (uint32_t)(slab * 16 * 256) + brow;
            #pragma unroll
            for (int half = 0; half < 2; half++) {
                uint32_t bh[2][4];
                #pragma unroll
                for (int j2 = 0; j2 < 2; j2++) {
                    uint32_t nc = bnc0 + (uint32_t)(half * 4 + j2 * 2 + hsel);
                    ldsm4t(bh[j2], krow + (((nc & 8u) | ((nc ^ lam) & 7u)) << 4));
                }
                #pragma unroll
                for (int nt = 0; nt < 4; nt++) {
                    uint32_t h0 = bh[nt >> 1][(nt & 1) * 2], h1 = bh[nt >> 1][(nt & 1) * 2 + 1];
                    #pragma unroll
                    for (int mt = 0; mt < 2; mt++)
                        mma16816h(d[mt][half * 4 + nt], ah[mt], h0, h1);
                }
            }
        }
        __syncthreads();
    }

    // ---- epilogue: unscale + recentered rotary (Q,K) + store fp16 ----
    const float* ct = (z == 0) ? g_cosQ : g_cosK;
    const float* st = (z == 0) ? g_sinQ : g_sinK;
    __half* Oqk = (z == 0) ? g_Qh : g_Kh;
    const float DS = 0.0009765625f;     // 2^-10
    int mrb = m0 + wm * 32 + (l >> 2);
    int ncb = n0 + wn * 64 + (l & 3) * 2;
    #pragma unroll
    for (int mt = 0; mt < 2; mt++)
        #pragma unroll
        for (int r2 = 0; r2 < 2; r2++) {
            int m = mrb + mt * 16 + r2 * 8;
            int pos = m & (SEQ - 1);
            #pragma unroll
            for (int nt = 0; nt < 8; nt++) {
                int n = ncb + nt * 8;
                float v0 = d[mt][nt][r2 * 2] * DS, v1 = d[mt][nt][r2 * 2 + 1] * DS;
                if (z < 2) {
                    int j = n >> 1;
                    float C = ct[pos * 128 + j], S = st[pos * 128 + j];
                    float o0 = v0 * C - v1 * S;
                    float o1 = v1 * C + v0 * S;
                    *(uint32_t*)(Oqk + (size_t)m * HD + n) = fp16pair(o0, o1);
                } else {
                    *(uint32_t*)(g_Vf + (size_t)m * HD + n) = fp16pair(v0, v1);
                }
            }
        }
}

// ---------------- banded retention attention (all fp16 mma, single-S) ----------------
#define ASM_Q  0
#define ASM_B0 32768
#define ASM_B1 65536
#define ASM_S  98304
#define ATTN_SMEM 106496

__device__ __forceinline__ uint32_t swzV(uint32_t row, uint32_t cc) {    // 512B rows
    return row * 512u + (((cc & 24u) | ((cc ^ row) & 7u)) << 4);
}
__device__ __forceinline__ uint32_t swzS(uint32_t row, uint32_t cc) {    // 128B rows
    return row * 128u + (((cc ^ row) & 7u) << 4);
}

__global__ void __launch_bounds__(256, 2) attn_mma_kernel(float* __restrict__ out)
{
    extern __shared__ __align__(1024) char sm[];
    uint32_t smb = smem_u32(sm);
    int tid = threadIdx.x;
    int b = blockIdx.y;
    int q0 = blockIdx.x * 64;
    size_t base = (size_t)b * SEQ;

    #pragma unroll
    for (int i = 0; i < 8; i++) {
        int id = tid + i * 256;
        uint32_t row = (uint32_t)(id >> 5), cc = (uint32_t)(id & 31);
        cp16(smb + ASM_Q + swzV(row, cc), g_Qh + (base + q0 + row) * HD + cc * 8);
    }
    int kt_lo = q0 - DW; if (kt_lo < 0) kt_lo = 0;
    int nt = ((q0 - kt_lo) >> 6) + 1;
    #pragma unroll
    for (int i = 0; i < 8; i++) {
        int id = tid + i * 256;
        uint32_t row = (uint32_t)(id >> 5), cc = (uint32_t)(id & 31);
        cp16(smb + ASM_B0 + swzV(row, cc), g_Kh + (base + kt_lo + row) * HD + cc * 8);
    }
    CP_COMMIT();
    #pragma unroll
    for (int i = 0; i < 8; i++) {
        int id = tid + i * 256;
        uint32_t row = (uint32_t)(id >> 5), cc = (uint32_t)(id & 31);
        cp16(smb + ASM_B1 + swzV(row, cc), g_Vf + (base + kt_lo + row) * HD + cc * 8);
    }
    CP_COMMIT();

    int w = tid >> 5, l = tid & 31;
    int wm = w >> 2, wn = w & 3;
    uint32_t la = (uint32_t)(l & 15), hsel = (uint32_t)(l >> 4);

    float o[2][8][4];
    #pragma unroll
    for (int mt = 0; mt < 2; mt++)
        #pragma unroll
        for (int j = 0; j < 8; j++)
            #pragma unroll
            for (int r = 0; r < 4; r++) o[mt][j][r] = 0.0f;

    for (int it = 0; it < nt; it++) {
        int kt = kt_lo + it * 64;

        CP_WAIT(1);
        __syncthreads();

        // ---- phase 1: S = Q K^T, single fp16 mma ----
        float sacc[2][2][4];
        #pragma unroll
        for (int mt = 0; mt < 2; mt++)
            #pragma unroll
            for (int nti = 0; nti < 2; nti++)
                #pragma unroll
                for (int r = 0; r < 4; r++) sacc[mt][nti][r] = 0.0f;

        #pragma unroll 4
        for (int ks = 0; ks < 16; ks++) {
            uint32_t qf[2][4];
            #pragma unroll
            for (int mt = 0; mt < 2; mt++) {
                uint32_t row = (uint32_t)(wm * 32 + mt * 16) + la;
                ldsm4(qf[mt], smb + ASM_Q + swzV(row, (uint32_t)(ks * 2) + hsel));
            }
            uint32_t kf[4];
            {
                uint32_t row = (uint32_t)(wn * 16) + la;
                ldsm4(kf, smb + ASM_B0 + swzV(row, (uint32_t)(ks * 2) + hsel));
            }
            #pragma unroll
            for (int mt = 0; mt < 2; mt++)
                #pragma unroll
                for (int nti = 0; nti < 2; nti++)
                    mma16816h(sacc[mt][nti], qf[mt], kf[nti], kf[nti + 2]);
        }

        // ---- decay + single fp16 S staging ----
        int dq = q0 - kt;
        #pragma unroll
        for (int mt = 0; mt < 2; mt++)
            #pragma unroll
            for (int nti = 0; nti < 2; nti++) {
                int qr0 = wm * 32 + mt * 16 + (l >> 2);
                int key = wn * 16 + nti * 8 + (l & 3) * 2;
                #pragma unroll
                for (int h = 0; h < 2; h++) {
                    int q = qr0 + 8 * h;
                    int e0 = dq + q - key;
                    float g0 = (e0 >= 0) ? g_gamma[e0] : 0.0f;
                    float g1 = (e0 >= 1) ? g_gamma[e0 - 1] : 0.0f;
                    float s0 = sacc[mt][nti][2 * h] * g0;
                    float s1 = sacc[mt][nti][2 * h + 1] * g1;
                    uint32_t cc = (uint32_t)(key >> 3);
                    uint32_t inb = (uint32_t)((key & 7) * 2);
                    *(uint32_t*)(sm + ASM_S + swzS((uint32_t)q, cc) + inb) = fp16pair(s0, s1);
                }
            }
        __syncthreads();

        if (it + 1 < nt) {
            #pragma unroll
            for (int i = 0; i < 8; i++) {
                int id = tid + i * 256;
                uint32_t row = (uint32_t)(id >> 5), cc = (uint32_t)(id & 31);
                cp16(smb + ASM_B0 + swzV(row, cc),
                     g_Kh + (base + kt + 64 + row) * HD + cc * 8);
            }
            CP_COMMIT();
            CP_WAIT(1);
        } else {
            CP_WAIT(0);
        }
        __syncthreads();

        // ---- phase 2: O += S V, single fp16 ----
        #pragma unroll
        for (int ks2 = 0; ks2 < 4; ks2++) {
            uint32_t sh[2][4];
            #pragma unroll
            for (int mt = 0; mt < 2; mt++) {
                uint32_t row = (uint32_t)(wm * 32 + mt * 16) + la;
                ldsm4(sh[mt], smb + ASM_S + swzS(row, (uint32_t)(ks2 * 2) + hsel));
            }
            uint32_t vrow = (uint32_t)(ks2 * 16) + la;
            #pragma unroll
            for (int j = 0; j < 4; j++) {
                uint32_t vh[4];
                uint32_t cc = (uint32_t)(wn * 8 + j * 2) + hsel;
                ldsm4t(vh, smb + ASM_B1 + swzV(vrow, cc));
                #pragma unroll
                for (int nti = 0; nti < 2; nti++) {
                    uint32_t b0 = vh[nti * 2], b1 = vh[nti * 2 + 1];
                    #pragma unroll
                    for (int mt = 0; mt < 2; mt++)
                        mma16816h(o[mt][j * 2 + nti], sh[mt], b0, b1);
                }
            }
        }
        __syncthreads();

        if (it + 1 < nt) {
            #pragma unroll
            for (int i = 0; i < 8; i++) {
                int id = tid + i * 256;
                uint32_t row = (uint32_t)(id >> 5), cc = (uint32_t)(id & 31);
                cp16(smb + ASM_B1 + swzV(row, cc),
                     g_Vf + (base + kt + 64 + row) * HD + cc * 8);
            }
            CP_COMMIT();
        }
    }

    #pragma unroll
    for (int mt = 0; mt < 2; mt++)
        #pragma unroll
        for (int h = 0; h < 2; h++) {
            int q = q0 + wm * 32 + mt * 16 + (l >> 2) + 8 * h;
            size_t ro = (base + q) * (size_t)HD;
            #pragma unroll
            for (int j = 0; j < 8; j++) {
                int vd = wn * 64 + j * 8 + (l & 3) * 2;
                float2 v;
                v.x = o[mt][j][2 * h];
                v.y = o[mt][j][2 * h + 1];
                *(float2*)(out + ro + vd) = v;
            }
        }
}

// ---------------- launch ----------------
extern "C" void kernel_launch(void* const* d_in, const int* in_sizes, int n_in,
                              void* d_out, int out_size) {
    const float* X  = (const float*)d_in[0];
    const float* WQ = (const float*)d_in[1];
    const float* WK = (const float*)d_in[2];
    const float* WV = (const float*)d_in[3];
    float* out = (float*)d_out;

    prep_kernel<<<PREP_BX + PREP_BW + PREP_BT, 256>>>(X, WQ, WK, WV);

    cudaFuncSetAttribute(proj_mma_kernel, cudaFuncAttributeMaxDynamicSharedMemorySize,
                         PROJ_SMEM);
    dim3 pg(6, MTOT / 128);
    proj_mma_kernel<<<pg, 256, PROJ_SMEM>>>();

    cudaFuncSetAttribute(attn_mma_kernel, cudaFuncAttributeMaxDynamicSharedMemorySize,
                         ATTN_SMEM);
    dim3 ag(SEQ / 64, NB);
    attn_mma_kernel<<<ag, 256, ATTN_SMEM>>>(out);
}

// round 17
// speedup vs baseline: 1.7790x; 1.7790x over previous
#include <cuda_runtime.h>
#include <cuda_bf16.h>
#include <cuda_fp16.h>
#include <math.h>
#include <stdint.h>

#define SEQ 4096
#define NB 4
#define HID 1024
#define HD 256
#define MTOT (NB*SEQ)
#define DW 256            // gamma^256: measured truncation cost ~1e-4 in quadrature

typedef unsigned long long u64;

// ---------------- static device scratch (no cudaMalloc allowed) ----------------
__device__ __half g_Qh[(size_t)MTOT*HD];    // recentered xpos scale, fp16
__device__ __half g_Kh[(size_t)MTOT*HD];
__device__ __half g_Vf[(size_t)MTOT*HD];
__device__ __half g_Xh[(size_t)MTOT*HID];
__device__ __half g_Wh[3*HID*HD];           // [z][k][n], W*1024 fp16
__device__ float g_cosQ[SEQ*128];
__device__ float g_sinQ[SEQ*128];
__device__ float g_cosK[SEQ*128];
__device__ float g_sinK[SEQ*128];
__device__ float g_gamma[SEQ];
__device__ double g_invf[128];
__device__ double g_l2sb[128];

// ---------------- mma / async helpers (baseline PTX, sm_80+ ISA only) ----------------
__device__ __forceinline__ uint32_t smem_u32(const void* p) {
    uint32_t a;
    asm("{ .reg .u64 t; cvta.to.shared.u64 t, %1; cvt.u32.u64 %0, t; }" : "=r"(a) : "l"(p));
    return a;
}
__device__ __forceinline__ void cp16(uint32_t dst, const void* src) {
    asm volatile("cp.async.cg.shared.global [%0], [%1], 16;" :: "r"(dst), "l"(src));
}
#define CP_COMMIT()  asm volatile("cp.async.commit_group;" ::: "memory")
#define CP_WAIT(n)   asm volatile("cp.async.wait_group %0;" :: "n"(n) : "memory")

__device__ __forceinline__ void ldsm4(uint32_t (&r)[4], uint32_t a) {
    asm volatile("ldmatrix.sync.aligned.m8n8.x4.shared.b16 {%0,%1,%2,%3}, [%4];"
                 : "=r"(r[0]), "=r"(r[1]), "=r"(r[2]), "=r"(r[3]) : "r"(a));
}
__device__ __forceinline__ void ldsm4t(uint32_t (&r)[4], uint32_t a) {
    asm volatile("ldmatrix.sync.aligned.m8n8.x4.trans.shared.b16 {%0,%1,%2,%3}, [%4];"
                 : "=r"(r[0]), "=r"(r[1]), "=r"(r[2]), "=r"(r[3]) : "r"(a));
}
__device__ __forceinline__ void mma16816h(float* d, const uint32_t* a, uint32_t b0, uint32_t b1) {
    asm volatile(
        "mma.sync.aligned.m16n8k16.row.col.f32.f16.f16.f32 "
        "{%0,%1,%2,%3}, {%4,%5,%6,%7}, {%8,%9}, {%0,%1,%2,%3};"
        : "+f"(d[0]), "+f"(d[1]), "+f"(d[2]), "+f"(d[3])
        : "r"(a[0]), "r"(a[1]), "r"(a[2]), "r"(a[3]), "r"(b0), "r"(b1));
}
__device__ __forceinline__ uint32_t fp16pair(float a, float b) {
    __half2 t; t.x = __float2half(a); t.y = __float2half(b);
    uint32_t r; asm("mov.b32 %0, %1;" : "=r"(r) : "r"(*(uint32_t*)&t)); return r;
}

// ---------------- fused prep stage 1: splitx | splitw + gamma + fp64 tables ----------------
// All parts independent. fp64 transcendental count stays tiny (128 + 4096),
// confined to the splitw-range blocks (R16 lesson: never recompute per-thread).
#define PREP_BX 8192               // splitx: X -> fp16, 8 floats/thread
#define PREP_BW 3072               // W*1024 -> fp16 (+ gamma, invf, l2sb)

__global__ void prep_kernel(const float* __restrict__ X,
                            const float* __restrict__ WQ,
                            const float* __restrict__ WK,
                            const float* __restrict__ WV) {
    int bid = blockIdx.x, tid = threadIdx.x;
    if (bid < PREP_BX) {
        // ---- splitx ----
        size_t i = (size_t)bid * 256 + tid;
        float4 a = ((const float4*)X)[2 * i];
        float4 b = ((const float4*)X)[2 * i + 1];
        uint4 o;
        o.x = fp16pair(a.x, a.y); o.y = fp16pair(a.z, a.w);
        o.z = fp16pair(b.x, b.y); o.w = fp16pair(b.z, b.w);
        ((uint4*)g_Xh)[i] = o;
    } else {
        // ---- splitw + constant tables ----
        int idx = (bid - PREP_BX) * 256 + tid;     // [z][k][n], 3*1024*256
        if (idx < 128) {
            g_invf[idx] = pow(10000.0, -(double)idx / 128.0);
            double sb = ((double)(2 * idx) + 0.4 * 256.0) / (1.4 * 256.0);
            g_l2sb[idx] = log2(sb);
        }
        if (idx < SEQ) g_gamma[idx] = (float)pow(0.96875, (double)idx);
        int z = idx >> 18;
        int kn = idx & 0x3FFFF;
        const float* W = (z == 0) ? WQ : (z == 1 ? WK : WV);
        g_Wh[idx] = __float2half(W[kn] * 1024.0f);
    }
}

// ---------------- xpos sin/cos tables, RECENTERED scale (reads fp64 tables) ----------------
__global__ void tables_kernel() {
    int pos = blockIdx.x, j = threadIdx.x;
    float invf = (float)g_invf[j];
    float arg = (float)pos * invf;
    double ad = (double)arg;
    double qd = rint(ad * 0.63661977236758134308);
    double rd = fma(qd, -1.5707963267948966, ad);
    rd = fma(qd, -6.123233995736766e-17, rd);
    int qi = ((long long)qd) & 3;
    float rf = (float)rd;
    float sr = sinf(rf), cr = cosf(rf);
    float s, c;
    if      (qi == 0) { s =  sr; c =  cr; }
    else if (qi == 1) { s =  cr; c = -sr; }
    else if (qi == 2) { s = -sr; c = -cr; }
    else              { s = -cr; c =  sr; }
    float p  = ((float)pos - 2048.0f) * (1.0f / 512.0f);   // recentered
    float l2 = (float)g_l2sb[j];
    float sc  = exp2f(p * l2);
    float isc = exp2f(-p * l2);
    int idx = pos * 128 + j;
    g_cosQ[idx] = c * sc;   g_sinQ[idx] = s * sc;
    g_cosK[idx] = c * isc;  g_sinK[idx] = s * isc;
}

// ---------------- projection GEMM (R14 champion: KC=64, 3-stage, 2 CTAs/SM) ----------------
#define PKC 64
#define PNSTG 16
#define PSTG_A 18432          // 128 rows x 144B (128B payload + 16B pad)
#define PSTG_B 16384          // 64 k-rows x 256B, swizzled
#define PSTG_BYTES (PSTG_A + PSTG_B)
#define PROJ_SMEM (3 * PSTG_BYTES)

__global__ void __launch_bounds__(256, 2) proj_mma_kernel()
{
    extern __shared__ __align__(1024) char sm[];
    uint32_t smb = smem_u32(sm);
    int tid = threadIdx.x;
    int z  = blockIdx.x >> 1;
    int n0 = (blockIdx.x & 1) * 128;
    int m0 = blockIdx.y * 128;

    const __half* Wh = g_Wh + (size_t)z * HID * HD + n0;

    const __half* srcA[4]; uint32_t dstA[4];
    #pragma unroll
    for (int i = 0; i < 4; i++) {
        int id = tid + i * 256;
        int m = id >> 3, c = id & 7;
        srcA[i] = g_Xh + (size_t)(m0 + m) * HID + c * 8;
        dstA[i] = (uint32_t)(m * 144 + c * 16);
    }
    const __half* srcB[4]; uint32_t dstB[4];
    #pragma unroll
    for (int i = 0; i < 4; i++) {
        int id = tid + i * 256;
        int k = id >> 4, cc = id & 15;
        srcB[i] = Wh + (size_t)k * HD + cc * 8;
        dstB[i] = (uint32_t)(PSTG_A + k * 256 +
                             ((uint32_t)((cc & 8) | ((cc ^ (k & 7)) & 7)) << 4));
    }

    int w = tid >> 5, l = tid & 31;
    int wm = w >> 1, wn = w & 1;
    int la = l & 15, hsel = l >> 4;
    uint32_t lam = (uint32_t)(la & 7);
    uint32_t brow = (uint32_t)(la * 256);
    uint32_t bnc0 = (uint32_t)(wn * 8);

    float d[2][8][4];
    #pragma unroll
    for (int mt = 0; mt < 2; mt++)
        #pragma unroll
        for (int nt = 0; nt < 8; nt++)
            #pragma unroll
            for (int r = 0; r < 4; r++) d[mt][nt][r] = 0.0f;

    #pragma unroll
    for (int p = 0; p < 2; p++) {
        uint32_t bb = smb + (uint32_t)p * PSTG_BYTES;
        int kt = p * PKC;
        #pragma unroll
        for (int i = 0; i < 4; i++) cp16(bb + dstA[i], srcA[i] + kt);
        #pragma unroll
        for (int i = 0; i < 4; i++) cp16(bb + dstB[i], srcB[i] + (size_t)kt * HD);
        CP_COMMIT();
    }

    int buf = 0, nbuf = 2;
    for (int s = 0; s < PNSTG; s++) {
        if (s + 2 < PNSTG) {
            uint32_t bb = smb + (uint32_t)nbuf * PSTG_BYTES;
            int kt = (s + 2) * PKC;
            #pragma unroll
            for (int i = 0; i < 4; i++) cp16(bb + dstA[i], srcA[i] + kt);
            #pragma unroll
            for (int i = 0; i < 4; i++) cp16(bb + dstB[i], srcB[i] + (size_t)kt * HD);
            CP_COMMIT();
            CP_WAIT(2);
        } else if (s + 1 < PNSTG) {
            CP_WAIT(1);
        } else {
            CP_WAIT(0);
        }
        __syncthreads();

        uint32_t AS = smb + (uint32_t)buf * PSTG_BYTES;
        uint32_t BS = AS + PSTG_A;
        buf = (buf + 1 == 3) ? 0 : buf + 1;
        nbuf = (nbuf + 1 == 3) ? 0 : nbuf + 1;

        #pragma unroll
        for (int slab = 0; slab < 4; slab++) {
            uint32_t ah[2][4];
            #pragma unroll
            for (int mt = 0; mt < 2; mt++) {
                uint32_t row = (uint32_t)(wm * 32 + mt * 16 + la);
                ldsm4(ah[mt], AS + row * 144 + (uint32_t)((slab * 2 + hsel) * 16));
            }
            uint32_t krow = BS + (uint32_t)(slab * 16 * 256) + brow;
            #pragma unroll
            for (int half = 0; half < 2; half++) {
                uint32_t bh[2][4];
                #pragma unroll
                for (int j2 = 0; j2 < 2; j2++) {
                    uint32_t nc = bnc0 + (uint32_t)(half * 4 + j2 * 2 + hsel);
                    ldsm4t(bh[j2], krow + (((nc & 8u) | ((nc ^ lam) & 7u)) << 4));
                }
                #pragma unroll
                for (int nt = 0; nt < 4; nt++) {
                    uint32_t h0 = bh[nt >> 1][(nt & 1) * 2], h1 = bh[nt >> 1][(nt & 1) * 2 + 1];
                    #pragma unroll
                    for (int mt = 0; mt < 2; mt++)
                        mma16816h(d[mt][half * 4 + nt], ah[mt], h0, h1);
                }
            }
        }
        __syncthreads();
    }

    const float* ct = (z == 0) ? g_cosQ : g_cosK;
    const float* st = (z == 0) ? g_sinQ : g_sinK;
    __half* Oqk = (z == 0) ? g_Qh : g_Kh;
    const float DS = 0.0009765625f;     // 2^-10
    int mrb = m0 + wm * 32 + (l >> 2);
    int ncb = n0 + wn * 64 + (l & 3) * 2;
    #pragma unroll
    for (int mt = 0; mt < 2; mt++)
        #pragma unroll
        for (int r2 = 0; r2 < 2; r2++) {
            int m = mrb + mt * 16 + r2 * 8;
            int pos = m & (SEQ - 1);
            #pragma unroll
            for (int nt = 0; nt < 8; nt++) {
                int n = ncb + nt * 8;
                float v0 = d[mt][nt][r2 * 2] * DS, v1 = d[mt][nt][r2 * 2 + 1] * DS;
                if (z < 2) {
                    int j = n >> 1;
                    float C = ct[pos * 128 + j], S = st[pos * 128 + j];
                    float o0 = v0 * C - v1 * S;
                    float o1 = v1 * C + v0 * S;
                    *(uint32_t*)(Oqk + (size_t)m * HD + n) = fp16pair(o0, o1);
                } else {
                    *(uint32_t*)(g_Vf + (size_t)m * HD + n) = fp16pair(v0, v1);
                }
            }
        }
}

// ---------------- banded retention attention (all fp16 mma, single-S) ----------------
#define ASM_Q  0
#define ASM_B0 32768
#define ASM_B1 65536
#define ASM_S  98304
#define ATTN_SMEM 106496

__device__ __forceinline__ uint32_t swzV(uint32_t row, uint32_t cc) {    // 512B rows
    return row * 512u + (((cc & 24u) | ((cc ^ row) & 7u)) << 4);
}
__device__ __forceinline__ uint32_t swzS(uint32_t row, uint32_t cc) {    // 128B rows
    return row * 128u + (((cc ^ row) & 7u) << 4);
}

__global__ void __launch_bounds__(256, 2) attn_mma_kernel(float* __restrict__ out)
{
    extern __shared__ __align__(1024) char sm[];
    uint32_t smb = smem_u32(sm);
    int tid = threadIdx.x;
    int b = blockIdx.y;
    int q0 = blockIdx.x * 64;
    size_t base = (size_t)b * SEQ;

    #pragma unroll
    for (int i = 0; i < 8; i++) {
        int id = tid + i * 256;
        uint32_t row = (uint32_t)(id >> 5), cc = (uint32_t)(id & 31);
        cp16(smb + ASM_Q + swzV(row, cc), g_Qh + (base + q0 + row) * HD + cc * 8);
    }
    int kt_lo = q0 - DW; if (kt_lo < 0) kt_lo = 0;
    int nt = ((q0 - kt_lo) >> 6) + 1;
    #pragma unroll
    for (int i = 0; i < 8; i++) {
        int id = tid + i * 256;
        uint32_t row = (uint32_t)(id >> 5), cc = (uint32_t)(id & 31);
        cp16(smb + ASM_B0 + swzV(row, cc), g_Kh + (base + kt_lo + row) * HD + cc * 8);
    }
    CP_COMMIT();
    #pragma unroll
    for (int i = 0; i < 8; i++) {
        int id = tid + i * 256;
        uint32_t row = (uint32_t)(id >> 5), cc = (uint32_t)(id & 31);
        cp16(smb + ASM_B1 + swzV(row, cc), g_Vf + (base + kt_lo + row) * HD + cc * 8);
    }
    CP_COMMIT();

    int w = tid >> 5, l = tid & 31;
    int wm = w >> 2, wn = w & 3;
    uint32_t la = (uint32_t)(l & 15), hsel = (uint32_t)(l >> 4);

    float o[2][8][4];
    #pragma unroll
    for (int mt = 0; mt < 2; mt++)
        #pragma unroll
        for (int j = 0; j < 8; j++)
            #pragma unroll
            for (int r = 0; r < 4; r++) o[mt][j][r] = 0.0f;

    for (int it = 0; it < nt; it++) {
        int kt = kt_lo + it * 64;

        CP_WAIT(1);
        __syncthreads();

        float sacc[2][2][4];
        #pragma unroll
        for (int mt = 0; mt < 2; mt++)
            #pragma unroll
            for (int nti = 0; nti < 2; nti++)
                #pragma unroll
                for (int r = 0; r < 4; r++) sacc[mt][nti][r] = 0.0f;

        #pragma unroll 4
        for (int ks = 0; ks < 16; ks++) {
            uint32_t qf[2][4];
            #pragma unroll
            for (int mt = 0; mt < 2; mt++) {
                uint32_t row = (uint32_t)(wm * 32 + mt * 16) + la;
                ldsm4(qf[mt], smb + ASM_Q + swzV(row, (uint32_t)(ks * 2) + hsel));
            }
            uint32_t kf[4];
            {
                uint32_t row = (uint32_t)(wn * 16) + la;
                ldsm4(kf, smb + ASM_B0 + swzV(row, (uint32_t)(ks * 2) + hsel));
            }
            #pragma unroll
            for (int mt = 0; mt < 2; mt++)
                #pragma unroll
                for (int nti = 0; nti < 2; nti++)
                    mma16816h(sacc[mt][nti], qf[mt], kf[nti], kf[nti + 2]);
        }

        int dq = q0 - kt;
        #pragma unroll
        for (int mt = 0; mt < 2; mt++)
            #pragma unroll
            for (int nti = 0; nti < 2; nti++) {
                int qr0 = wm * 32 + mt * 16 + (l >> 2);
                int key = wn * 16 + nti * 8 + (l & 3) * 2;
                #pragma unroll
                for (int h = 0; h < 2; h++) {
                    int q = qr0 + 8 * h;
                    int e0 = dq + q - key;
                    float g0 = (e0 >= 0) ? g_gamma[e0] : 0.0f;
                    float g1 = (e0 >= 1) ? g_gamma[e0 - 1] : 0.0f;
                    float s0 = sacc[mt][nti][2 * h] * g0;
                    float s1 = sacc[mt][nti][2 * h + 1] * g1;
                    uint32_t cc = (uint32_t)(key >> 3);
                    uint32_t inb = (uint32_t)((key & 7) * 2);
                    *(uint32_t*)(sm + ASM_S + swzS((uint32_t)q, cc) + inb) = fp16pair(s0, s1);
                }
            }
        __syncthreads();

        if (it + 1 < nt) {
            #pragma unroll
            for (int i = 0; i < 8; i++) {
                int id = tid + i * 256;
                uint32_t row = (uint32_t)(id >> 5), cc = (uint32_t)(id & 31);
                cp16(smb + ASM_B0 + swzV(row, cc),
                     g_Kh + (base + kt + 64 + row) * HD + cc * 8);
            }
            CP_COMMIT();
            CP_WAIT(1);
        } else {
            CP_WAIT(0);
        }
        __syncthreads();

        #pragma unroll
        for (int ks2 = 0; ks2 < 4; ks2++) {
            uint32_t sh[2][4];
            #pragma unroll
            for (int mt = 0; mt < 2; mt++) {
                uint32_t row = (uint32_t)(wm * 32 + mt * 16) + la;
                ldsm4(sh[mt], smb + ASM_S + swzS(row, (uint32_t)(ks2 * 2) + hsel));
            }
            uint32_t vrow = (uint32_t)(ks2 * 16) + la;
            #pragma unroll
            for (int j = 0; j < 4; j++) {
                uint32_t vh[4];
                uint32_t cc = (uint32_t)(wn * 8 + j * 2) + hsel;
                ldsm4t(vh, smb + ASM_B1 + swzV(vrow, cc));
                #pragma unroll
                for (int nti = 0; nti < 2; nti++) {
                    uint32_t b0 = vh[nti * 2], b1 = vh[nti * 2 + 1];
                    #pragma unroll
                    for (int mt = 0; mt < 2; mt++)
                        mma16816h(o[mt][j * 2 + nti], sh[mt], b0, b1);
                }
            }
        }
        __syncthreads();

        if (it + 1 < nt) {
            #pragma unroll
            for (int i = 0; i < 8; i++) {
                int id = tid + i * 256;
                uint32_t row = (uint32_t)(id >> 5), cc = (uint32_t)(id & 31);
                cp16(smb + ASM_B1 + swzV(row, cc),
                     g_Vf + (base + kt + 64 + row) * HD + cc * 8);
            }
            CP_COMMIT();
        }
    }

    #pragma unroll
    for (int mt = 0; mt < 2; mt++)
        #pragma unroll
        for (int h = 0; h < 2; h++) {
            int q = q0 + wm * 32 + mt * 16 + (l >> 2) + 8 * h;
            size_t ro = (base + q) * (size_t)HD;
            #pragma unroll
            for (int j = 0; j < 8; j++) {
                int vd = wn * 64 + j * 8 + (l & 3) * 2;
                float2 v;
                v.x = o[mt][j][2 * h];
                v.y = o[mt][j][2 * h + 1];
                *(float2*)(out + ro + vd) = v;
            }
        }
}

// ---------------- launch ----------------
extern "C" void kernel_launch(void* const* d_in, const int* in_sizes, int n_in,
                              void* d_out, int out_size) {
    const float* X  = (const float*)d_in[0];
    const float* WQ = (const float*)d_in[1];
    const float* WK = (const float*)d_in[2];
    const float* WV = (const float*)d_in[3];
    float* out = (float*)d_out;

    prep_kernel<<<PREP_BX + PREP_BW, 256>>>(X, WQ, WK, WV);
    tables_kernel<<<SEQ, 128>>>();

    cudaFuncSetAttribute(proj_mma_kernel, cudaFuncAttributeMaxDynamicSharedMemorySize,
                         PROJ_SMEM);
    dim3 pg(6, MTOT / 128);
    proj_mma_kernel<<<pg, 256, PROJ_SMEM>>>();

    cudaFuncSetAttribute(attn_mma_kernel, cudaFuncAttributeMaxDynamicSharedMemorySize,
                         ATTN_SMEM);
    dim3 ag(SEQ / 64, NB);
    attn_mma_kernel<<<ag, 256, ATTN_SMEM>>>(out);
}